// round 2
// baseline (speedup 1.0000x reference)
#include <cuda_runtime.h>
#include <math.h>

#define SPATIAL 196608           // 24*64*128
#define NELEM_B (32 * SPATIAL)   // per-batch elements of cost
#define NB_MAIN 296              // main kernel blocks (148 per batch)

static __device__ double g_sum1[2], g_sumsq1[2], g_sum2[2], g_sumsq2[2];
static __device__ float g_K[2][2][256][16];   // [b][h][n][c], pre-scaled by 0.25
static __device__ float g_V[2][2][256][16];   // [b][h][n][j]

__global__ void zero_acc_kernel() {
    int i = threadIdx.x;
    if (i < 2) { g_sum1[i] = 0.0; g_sumsq1[i] = 0.0; g_sum2[i] = 0.0; g_sumsq2[i] = 0.0; }
}

// GroupNorm-1 statistics over cost, per batch. grid = 2*512 blocks, 256 thr.
__global__ void stats1_kernel(const float* __restrict__ cost) {
    int b   = blockIdx.x >> 9;
    int blk = blockIdx.x & 511;
    const float4* p = (const float4*)(cost + (size_t)b * NELEM_B);
    const int n4 = NELEM_B / 4;
    float s = 0.f, ss = 0.f;
    for (int i = blk * 256 + threadIdx.x; i < n4; i += 512 * 256) {
        float4 v = p[i];
        s  += (v.x + v.y) + (v.z + v.w);
        ss += (v.x * v.x + v.y * v.y) + (v.z * v.z + v.w * v.w);
    }
    __shared__ float rs[256], rss[256];
    rs[threadIdx.x] = s; rss[threadIdx.x] = ss;
    __syncthreads();
    for (int st = 128; st > 0; st >>= 1) {
        if (threadIdx.x < st) { rs[threadIdx.x] += rs[threadIdx.x + st]; rss[threadIdx.x] += rss[threadIdx.x + st]; }
        __syncthreads();
    }
    if (threadIdx.x == 0) {
        atomicAdd(&g_sum1[b],   (double)rs[0]);
        atomicAdd(&g_sumsq1[b], (double)rss[0]);
    }
}

// K/V projections: k[b,h,c,n] = sum_fc Wk[h*16+c,fc] * feat[b,fc,n]  (K scaled by 0.25)
// grid = 64 blocks * 256 threads = 16384 = 2*2*256*16 outputs
__global__ void kv_kernel(const float* __restrict__ feat,
                          const float* __restrict__ Wk,
                          const float* __restrict__ Wv) {
    int idx = blockIdx.x * 256 + threadIdx.x;
    int c = idx & 15;
    int n = (idx >> 4) & 255;
    int h = (idx >> 12) & 1;
    int b = idx >> 13;
    const float* f  = feat + (size_t)b * 256 * 256 + n;  // stride 256 per fc
    const float* wk = Wk + (h * 16 + c) * 256;
    const float* wv = Wv + (h * 16 + c) * 256;
    float sk = 0.f, sv = 0.f;
    #pragma unroll 8
    for (int fc = 0; fc < 256; ++fc) {
        float fv = f[(size_t)fc * 256];
        sk = fmaf(wk[fc], fv, sk);
        sv = fmaf(wv[fc], fv, sv);
    }
    g_K[b][h][n][c] = sk * 0.25f;   // DQK^-0.5 = 0.25 folded in
    g_V[b][h][n][c] = sv;
}

// Fused: GN1-normalize -> q proj -> online-softmax attention -> Wo -> residual
// Also accumulates GN2 statistics of y = cost + gamma*out.
__global__ void __launch_bounds__(256, 2) main_kernel(
    const float* __restrict__ cost,
    const float* __restrict__ Wq,
    const float* __restrict__ Wo,
    const float* __restrict__ gnw,
    const float* __restrict__ gnb,
    const float* __restrict__ gammap,
    float* __restrict__ out)
{
    extern __shared__ float sm[];
    float* sK  = sm;            // 8192 floats: [h][n][c]
    float* sV  = sm + 8192;     // 8192
    float* sWq = sm + 16384;    // 1024
    float* sWo = sm + 17408;    // 1024
    float* sGw = sm + 18432;    // 32  (GN1 scale folded: is1 * w[c])
    float* sGb = sm + 18464;    // 32  (GN1 shift folded)

    const int b   = blockIdx.x & 1;
    const int bi  = blockIdx.x >> 1;
    const int nb  = gridDim.x >> 1;
    const int tid = threadIdx.x;

    const float* gKb = &g_K[b][0][0][0];
    const float* gVb = &g_V[b][0][0][0];
    for (int i = tid; i < 8192; i += 256) { sK[i] = gKb[i]; sV[i] = gVb[i]; }
    for (int i = tid; i < 1024; i += 256) { sWq[i] = Wq[i]; sWo[i] = Wo[i]; }
    if (tid < 32) {
        double mu  = g_sum1[b] / (double)NELEM_B;
        double var = g_sumsq1[b] / (double)NELEM_B - mu * mu;
        float is = (float)(1.0 / sqrt(var + 1e-5));
        float sc = gnw[tid] * is;
        sGw[tid] = sc;
        sGb[tid] = gnb[tid] - (float)mu * sc;
    }
    __syncthreads();

    const float gamma = *gammap;
    const float* costb = cost + (size_t)b * NELEM_B;
    float* outb = out + (size_t)b * NELEM_B;

    float lsum = 0.f, lsumsq = 0.f;

    for (int v = bi * 256 + tid; v < SPATIAL; v += nb * 256) {
        // normalized input channels
        float ci[32];
        #pragma unroll
        for (int c = 0; c < 32; ++c)
            ci[c] = fmaf(costb[(size_t)c * SPATIAL + v], sGw[c], sGb[c]);

        // q projection (32x32)
        float q[32];
        #pragma unroll
        for (int o = 0; o < 32; ++o) {
            float s0 = 0.f, s1 = 0.f, s2 = 0.f, s3 = 0.f;
            #pragma unroll
            for (int c = 0; c < 32; c += 4) {
                s0 = fmaf(sWq[o * 32 + c + 0], ci[c + 0], s0);
                s1 = fmaf(sWq[o * 32 + c + 1], ci[c + 1], s1);
                s2 = fmaf(sWq[o * 32 + c + 2], ci[c + 2], s2);
                s3 = fmaf(sWq[o * 32 + c + 3], ci[c + 3], s3);
            }
            q[o] = (s0 + s1) + (s2 + s3);
        }

        // attention per head, online softmax (logits are O(0.3): no max shift needed)
        float ao[32];
        #pragma unroll
        for (int h = 0; h < 2; ++h) {
            const float4* Kh = reinterpret_cast<const float4*>(sK + h * 4096);
            const float4* Vh = reinterpret_cast<const float4*>(sV + h * 4096);
            float denom = 0.f;
            float acc[16];
            #pragma unroll
            for (int j = 0; j < 16; ++j) acc[j] = 0.f;

            #pragma unroll 2
            for (int n = 0; n < 256; ++n) {
                float4 k0 = Kh[n * 4 + 0], k1 = Kh[n * 4 + 1], k2 = Kh[n * 4 + 2], k3 = Kh[n * 4 + 3];
                float l0 = fmaf(q[h*16+0],  k0.x, fmaf(q[h*16+1],  k0.y, fmaf(q[h*16+2],  k0.z, q[h*16+3]  * k0.w)));
                float l1 = fmaf(q[h*16+4],  k1.x, fmaf(q[h*16+5],  k1.y, fmaf(q[h*16+6],  k1.z, q[h*16+7]  * k1.w)));
                float l2 = fmaf(q[h*16+8],  k2.x, fmaf(q[h*16+9],  k2.y, fmaf(q[h*16+10], k2.z, q[h*16+11] * k2.w)));
                float l3 = fmaf(q[h*16+12], k3.x, fmaf(q[h*16+13], k3.y, fmaf(q[h*16+14], k3.z, q[h*16+15] * k3.w)));
                float e = __expf((l0 + l1) + (l2 + l3));
                denom += e;
                float4 v0 = Vh[n * 4 + 0], v1 = Vh[n * 4 + 1], v2 = Vh[n * 4 + 2], v3 = Vh[n * 4 + 3];
                acc[0]  = fmaf(e, v0.x, acc[0]);  acc[1]  = fmaf(e, v0.y, acc[1]);
                acc[2]  = fmaf(e, v0.z, acc[2]);  acc[3]  = fmaf(e, v0.w, acc[3]);
                acc[4]  = fmaf(e, v1.x, acc[4]);  acc[5]  = fmaf(e, v1.y, acc[5]);
                acc[6]  = fmaf(e, v1.z, acc[6]);  acc[7]  = fmaf(e, v1.w, acc[7]);
                acc[8]  = fmaf(e, v2.x, acc[8]);  acc[9]  = fmaf(e, v2.y, acc[9]);
                acc[10] = fmaf(e, v2.z, acc[10]); acc[11] = fmaf(e, v2.w, acc[11]);
                acc[12] = fmaf(e, v3.x, acc[12]); acc[13] = fmaf(e, v3.y, acc[13]);
                acc[14] = fmaf(e, v3.z, acc[14]); acc[15] = fmaf(e, v3.w, acc[15]);
            }
            float inv = 1.f / denom;
            #pragma unroll
            for (int j = 0; j < 16; ++j) ao[h * 16 + j] = acc[j] * inv;
        }

        // Wo projection + residual + GN2 stats
        #pragma unroll
        for (int c = 0; c < 32; ++c) {
            float s0 = 0.f, s1 = 0.f, s2 = 0.f, s3 = 0.f;
            #pragma unroll
            for (int m = 0; m < 32; m += 4) {
                s0 = fmaf(sWo[c * 32 + m + 0], ao[m + 0], s0);
                s1 = fmaf(sWo[c * 32 + m + 1], ao[m + 1], s1);
                s2 = fmaf(sWo[c * 32 + m + 2], ao[m + 2], s2);
                s3 = fmaf(sWo[c * 32 + m + 3], ao[m + 3], s3);
            }
            float y = fmaf(gamma, (s0 + s1) + (s2 + s3), costb[(size_t)c * SPATIAL + v]);
            outb[(size_t)c * SPATIAL + v] = y;
            lsum += y;
            lsumsq = fmaf(y, y, lsumsq);
        }
    }

    __shared__ float rs[256], rss[256];
    rs[tid] = lsum; rss[tid] = lsumsq;
    __syncthreads();
    for (int st = 128; st > 0; st >>= 1) {
        if (tid < st) { rs[tid] += rs[tid + st]; rss[tid] += rss[tid + st]; }
        __syncthreads();
    }
    if (tid == 0) {
        atomicAdd(&g_sum2[b],   (double)rs[0]);
        atomicAdd(&g_sumsq2[b], (double)rss[0]);
    }
}

// Final GroupNorm over y (in place on d_out)
__global__ void gn2_kernel(float* __restrict__ y,
                           const float* __restrict__ w,
                           const float* __restrict__ bb) {
    const double Nd = (double)NELEM_B;
    double mu0 = g_sum2[0] / Nd, v0d = g_sumsq2[0] / Nd - mu0 * mu0;
    double mu1 = g_sum2[1] / Nd, v1d = g_sumsq2[1] / Nd - mu1 * mu1;
    float is0 = (float)(1.0 / sqrt(v0d + 1e-5));
    float is1 = (float)(1.0 / sqrt(v1d + 1e-5));
    float m0 = (float)mu0, m1 = (float)mu1;

    const int half4  = NELEM_B / 4;
    const int total4 = 2 * half4;
    float4* p = (float4*)y;
    for (int i = blockIdx.x * blockDim.x + threadIdx.x; i < total4; i += gridDim.x * blockDim.x) {
        int b = (i >= half4);
        int e = (i - b * half4) * 4;
        int c = e / SPATIAL;            // all 4 lanes share c (SPATIAL % 4 == 0)
        float is = b ? is1 : is0;
        float mu = b ? m1  : m0;
        float sc = w[c] * is;
        float sh = bb[c] - mu * sc;
        float4 val = p[i];
        val.x = fmaf(val.x, sc, sh);
        val.y = fmaf(val.y, sc, sh);
        val.z = fmaf(val.z, sc, sh);
        val.w = fmaf(val.w, sc, sh);
        p[i] = val;
    }
}

extern "C" void kernel_launch(void* const* d_in, const int* in_sizes, int n_in,
                              void* d_out, int out_size) {
    const float* cost   = (const float*)d_in[0];
    const float* feat   = (const float*)d_in[1];
    const float* Wq     = (const float*)d_in[2];
    const float* Wk     = (const float*)d_in[3];
    const float* Wv     = (const float*)d_in[4];
    const float* Wo     = (const float*)d_in[5];
    const float* gn_in_w  = (const float*)d_in[6];
    const float* gn_in_b  = (const float*)d_in[7];
    const float* gn_out_w = (const float*)d_in[8];
    const float* gn_out_b = (const float*)d_in[9];
    const float* gamma    = (const float*)d_in[10];
    float* out = (float*)d_out;

    cudaFuncSetAttribute(main_kernel, cudaFuncAttributeMaxDynamicSharedMemorySize, 18496 * 4);

    zero_acc_kernel<<<1, 32>>>();
    stats1_kernel<<<1024, 256>>>(cost);
    kv_kernel<<<64, 256>>>(feat, Wk, Wv);
    main_kernel<<<NB_MAIN, 256, 18496 * 4>>>(cost, Wq, Wo, gn_in_w, gn_in_b, gamma, out);
    gn2_kernel<<<2368, 256>>>(out, gn_out_w, gn_out_b);
}

// round 6
// speedup vs baseline: 4.2832x; 4.2832x over previous
#include <cuda_runtime.h>
#include <cuda_bf16.h>
#include <cstdint>
#include <math.h>

#define SPATIAL 196608           // 24*64*128
#define NELEM_B (32 * SPATIAL)   // per-batch elements of cost

static __device__ double g_sum1[2], g_sumsq1[2], g_sum2[2], g_sumsq2[2];
static __device__ float g_K[2][2][256][16];   // [b][h][n][c], pre-scaled by 0.25
static __device__ float g_V[2][2][256][16];   // [b][h][n][j]

__global__ void zero_acc_kernel() {
    int i = threadIdx.x;
    if (i < 2) { g_sum1[i] = 0.0; g_sumsq1[i] = 0.0; g_sum2[i] = 0.0; g_sumsq2[i] = 0.0; }
}

// GroupNorm-1 statistics over cost, per batch. grid = 2*512 blocks, 256 thr.
__global__ void stats1_kernel(const float* __restrict__ cost) {
    int b   = blockIdx.x >> 9;
    int blk = blockIdx.x & 511;
    const float4* p = (const float4*)(cost + (size_t)b * NELEM_B);
    const int n4 = NELEM_B / 4;
    float s = 0.f, ss = 0.f;
    for (int i = blk * 256 + threadIdx.x; i < n4; i += 512 * 256) {
        float4 v = p[i];
        s  += (v.x + v.y) + (v.z + v.w);
        ss += (v.x * v.x + v.y * v.y) + (v.z * v.z + v.w * v.w);
    }
    __shared__ float rs[256], rss[256];
    rs[threadIdx.x] = s; rss[threadIdx.x] = ss;
    __syncthreads();
    for (int st = 128; st > 0; st >>= 1) {
        if (threadIdx.x < st) { rs[threadIdx.x] += rs[threadIdx.x + st]; rss[threadIdx.x] += rss[threadIdx.x + st]; }
        __syncthreads();
    }
    if (threadIdx.x == 0) {
        atomicAdd(&g_sum1[b],   (double)rs[0]);
        atomicAdd(&g_sumsq1[b], (double)rss[0]);
    }
}

// K/V projections. grid = 64 * 256 threads = 16384 = 2*2*256*16 outputs
__global__ void kv_kernel(const float* __restrict__ feat,
                          const float* __restrict__ Wk,
                          const float* __restrict__ Wv) {
    int idx = blockIdx.x * 256 + threadIdx.x;
    int c = idx & 15;
    int n = (idx >> 4) & 255;
    int h = (idx >> 12) & 1;
    int b = idx >> 13;
    const float* f  = feat + (size_t)b * 256 * 256 + n;  // stride 256 per fc
    const float* wk = Wk + (h * 16 + c) * 256;
    const float* wv = Wv + (h * 16 + c) * 256;
    float sk = 0.f, sv = 0.f;
    #pragma unroll 8
    for (int fc = 0; fc < 256; ++fc) {
        float fv = f[(size_t)fc * 256];
        sk = fmaf(wk[fc], fv, sk);
        sv = fmaf(wv[fc], fv, sv);
    }
    g_K[b][h][n][c] = sk * 0.25f;   // DQK^-0.5 = 0.25 folded in
    g_V[b][h][n][c] = sv;
}

__device__ __forceinline__ void mma_bf16(float* c, const uint32_t* a, const uint32_t* b) {
    asm volatile(
        "mma.sync.aligned.m16n8k16.row.col.f32.bf16.bf16.f32 "
        "{%0,%1,%2,%3}, {%4,%5,%6,%7}, {%8,%9}, {%0,%1,%2,%3};\n"
        : "+f"(c[0]), "+f"(c[1]), "+f"(c[2]), "+f"(c[3])
        : "r"(a[0]), "r"(a[1]), "r"(a[2]), "r"(a[3]), "r"(b[0]), "r"(b[1]));
}

__device__ __forceinline__ uint32_t pack_bf16x2(float lo, float hi) {
    __nv_bfloat162 p = __float22bfloat162_rn(make_float2(lo, hi));
    return *(uint32_t*)&p;
}

// smem layout (bytes):
//   Ks  [2][256][24] bf16 : 0      .. 24576   (cols 0..15 valid)
//   Vt  [2][24][264] bf16 : 24576  .. 49920   (row16 = ones, 17..23 = zeros)
//   sWq [32][32] f32      : 49920  .. 54016
//   sWo [32][32] f32      : 54016  .. 58112
//   sGw/sGb 32 f32 each   : 58112  .. 58368
//   scratch 8 warps*4224B : 58368  .. 92160  (q bf16 [32][36] then o f32 [32][33])
#define SMEM_TOTAL 92160

__global__ void __launch_bounds__(256, 2) main_kernel(
    const float* __restrict__ cost,
    const float* __restrict__ Wq,
    const float* __restrict__ Wo,
    const float* __restrict__ gnw,
    const float* __restrict__ gnb,
    const float* __restrict__ gammap,
    float* __restrict__ out)
{
    extern __shared__ char sm[];
    __nv_bfloat16* Ks = (__nv_bfloat16*)sm;
    __nv_bfloat16* Vt = (__nv_bfloat16*)(sm + 24576);
    float* sWq = (float*)(sm + 49920);
    float* sWo = (float*)(sm + 54016);
    float* sGw = (float*)(sm + 58112);
    float* sGb = (float*)(sm + 58240);
    char*  scratch = sm + 58368;

    const int b   = blockIdx.x & 1;
    const int bi  = blockIdx.x >> 1;
    const int tid = threadIdx.x;
    const int wid = tid >> 5;
    const int lane = tid & 31;
    const int g  = lane >> 2;   // group id (row within fragment)
    const int tg = lane & 3;    // thread in group

    // ---- load K (token-major) and V (transposed, with ones column) to smem ----
    for (int i = tid; i < 512; i += 256) {          // i = h*256 + n
        int h = i >> 8, n = i & 255;
        const float* kp = &g_K[b][h][n][0];
        const float* vp = &g_V[b][h][n][0];
        __nv_bfloat16* krow = Ks + i * 24;
        #pragma unroll
        for (int c = 0; c < 16; ++c) krow[c] = __float2bfloat16(kp[c]);
        #pragma unroll
        for (int c = 0; c < 16; ++c) Vt[(h * 24 + c) * 264 + n] = __float2bfloat16(vp[c]);
        Vt[(h * 24 + 16) * 264 + n] = __float2bfloat16(1.0f);
        #pragma unroll
        for (int c = 17; c < 24; ++c) Vt[(h * 24 + c) * 264 + n] = __float2bfloat16(0.0f);
    }
    for (int i = tid; i < 1024; i += 256) { sWq[i] = Wq[i]; sWo[i] = Wo[i]; }
    if (tid < 32) {
        double mu  = g_sum1[b] / (double)NELEM_B;
        double var = g_sumsq1[b] / (double)NELEM_B - mu * mu;
        float is = (float)(1.0 / sqrt(var + 1e-5));
        float sc = gnw[tid] * is;
        sGw[tid] = sc;
        sGb[tid] = gnb[tid] - (float)mu * sc;
    }
    __syncthreads();

    const float gamma = *gammap;
    const float* costb = cost + (size_t)b * NELEM_B;
    float* outb = out + (size_t)b * NELEM_B;

    __nv_bfloat16* qsm = (__nv_bfloat16*)(scratch + wid * 4224);  // [32][36]
    float*         osm = (float*)(scratch + wid * 4224);          // [32][33]

    float lsum = 0.f, lsumsq = 0.f;

    for (int super = bi; super < 768; super += 148) {
        const int vbase = super * 256 + wid * 32;
        const int v = vbase + lane;

        // ---- scalar: GN1-normalize + q projection -> qsm (bf16) ----
        float ci[32];
        #pragma unroll
        for (int c = 0; c < 32; ++c)
            ci[c] = fmaf(costb[(size_t)c * SPATIAL + v], sGw[c], sGb[c]);
        #pragma unroll
        for (int o = 0; o < 32; ++o) {
            float s0 = 0.f, s1 = 0.f, s2 = 0.f, s3 = 0.f;
            #pragma unroll
            for (int c = 0; c < 32; c += 4) {
                s0 = fmaf(sWq[o * 32 + c + 0], ci[c + 0], s0);
                s1 = fmaf(sWq[o * 32 + c + 1], ci[c + 1], s1);
                s2 = fmaf(sWq[o * 32 + c + 2], ci[c + 2], s2);
                s3 = fmaf(sWq[o * 32 + c + 3], ci[c + 3], s3);
            }
            qsm[lane * 36 + o] = __float2bfloat16((s0 + s1) + (s2 + s3));
        }
        __syncwarp();

        // ---- load A (q) fragments for both heads, both m-tiles ----
        uint32_t aq[2][2][4];
        #pragma unroll
        for (int h = 0; h < 2; ++h)
            #pragma unroll
            for (int mt = 0; mt < 2; ++mt) {
                int r0 = mt * 16 + g, r1 = r0 + 8, c0 = h * 16 + tg * 2;
                aq[h][mt][0] = *(const uint32_t*)&qsm[r0 * 36 + c0];
                aq[h][mt][1] = *(const uint32_t*)&qsm[r1 * 36 + c0];
                aq[h][mt][2] = *(const uint32_t*)&qsm[r0 * 36 + c0 + 8];
                aq[h][mt][3] = *(const uint32_t*)&qsm[r1 * 36 + c0 + 8];
            }
        __syncwarp();   // qsm reads done; osm (same space) writes may begin

        // ---- attention per head ----
        #pragma unroll
        for (int h = 0; h < 2; ++h) {
            const __nv_bfloat16* Kh = Ks + h * 256 * 24;
            const __nv_bfloat16* Vh = Vt + h * 24 * 264;
            float co[2][3][4];
            #pragma unroll
            for (int mt = 0; mt < 2; ++mt)
                #pragma unroll
                for (int nv = 0; nv < 3; ++nv)
                    #pragma unroll
                    for (int i = 0; i < 4; ++i) co[mt][nv][i] = 0.f;

            for (int chk = 0; chk < 16; ++chk) {
                const int n0 = chk * 16;
                // K fragments (B operand of QK): 2 n-tiles
                uint32_t bk[2][2];
                #pragma unroll
                for (int nt = 0; nt < 2; ++nt) {
                    const __nv_bfloat16* kp = Kh + (n0 + nt * 8 + g) * 24 + tg * 2;
                    bk[nt][0] = *(const uint32_t*)kp;
                    bk[nt][1] = *(const uint32_t*)(kp + 8);
                }
                // logits
                float cl[2][2][4];
                #pragma unroll
                for (int mt = 0; mt < 2; ++mt)
                    #pragma unroll
                    for (int nt = 0; nt < 2; ++nt) {
                        #pragma unroll
                        for (int i = 0; i < 4; ++i) cl[mt][nt][i] = 0.f;
                        mma_bf16(cl[mt][nt], aq[h][mt], bk[nt]);
                    }
                // exp (logits are O(0.3): no max shift needed)
                #pragma unroll
                for (int mt = 0; mt < 2; ++mt)
                    #pragma unroll
                    for (int nt = 0; nt < 2; ++nt)
                        #pragma unroll
                        for (int i = 0; i < 4; ++i)
                            cl[mt][nt][i] = __expf(cl[mt][nt][i]);
                // P -> A fragments (C-frag/A-frag identity)
                uint32_t ap[2][4];
                #pragma unroll
                for (int mt = 0; mt < 2; ++mt) {
                    ap[mt][0] = pack_bf16x2(cl[mt][0][0], cl[mt][0][1]);
                    ap[mt][1] = pack_bf16x2(cl[mt][0][2], cl[mt][0][3]);
                    ap[mt][2] = pack_bf16x2(cl[mt][1][0], cl[mt][1][1]);
                    ap[mt][3] = pack_bf16x2(cl[mt][1][2], cl[mt][1][3]);
                }
                // V fragments (B operand of PV): 3 n-tiles (dv 0..23, col16=ones)
                uint32_t bv[3][2];
                #pragma unroll
                for (int nv = 0; nv < 3; ++nv) {
                    const __nv_bfloat16* vp = Vh + (nv * 8 + g) * 264 + n0 + tg * 2;
                    bv[nv][0] = *(const uint32_t*)vp;
                    bv[nv][1] = *(const uint32_t*)(vp + 8);
                }
                #pragma unroll
                for (int mt = 0; mt < 2; ++mt)
                    #pragma unroll
                    for (int nv = 0; nv < 3; ++nv)
                        mma_bf16(co[mt][nv], ap[mt], bv[nv]);
            }

            // normalize by denominator (ones-column, dv=16 -> tile 2, col 0) and store
            #pragma unroll
            for (int mt = 0; mt < 2; ++mt) {
                float dlo = __shfl_sync(0xffffffffu, co[mt][2][0], lane & ~3);
                float dhi = __shfl_sync(0xffffffffu, co[mt][2][2], lane & ~3);
                float ilo = 1.f / dlo, ihi = 1.f / dhi;
                int r0 = mt * 16 + g;
                #pragma unroll
                for (int nv = 0; nv < 2; ++nv) {
                    int c0 = h * 16 + nv * 8 + tg * 2;
                    osm[r0 * 33 + c0]           = co[mt][nv][0] * ilo;
                    osm[r0 * 33 + c0 + 1]       = co[mt][nv][1] * ilo;
                    osm[(r0 + 8) * 33 + c0]     = co[mt][nv][2] * ihi;
                    osm[(r0 + 8) * 33 + c0 + 1] = co[mt][nv][3] * ihi;
                }
            }
        }
        __syncwarp();

        // ---- epilogue: Wo projection + residual + GN2 stats ----
        float orow[32];
        #pragma unroll
        for (int m = 0; m < 32; ++m) orow[m] = osm[lane * 33 + m];
        #pragma unroll
        for (int c = 0; c < 32; ++c) {
            float s0 = 0.f, s1 = 0.f, s2 = 0.f, s3 = 0.f;
            #pragma unroll
            for (int m = 0; m < 32; m += 4) {
                s0 = fmaf(sWo[c * 32 + m + 0], orow[m + 0], s0);
                s1 = fmaf(sWo[c * 32 + m + 1], orow[m + 1], s1);
                s2 = fmaf(sWo[c * 32 + m + 2], orow[m + 2], s2);
                s3 = fmaf(sWo[c * 32 + m + 3], orow[m + 3], s3);
            }
            float y = fmaf(gamma, (s0 + s1) + (s2 + s3), costb[(size_t)c * SPATIAL + v]);
            outb[(size_t)c * SPATIAL + v] = y;
            lsum += y;
            lsumsq = fmaf(y, y, lsumsq);
        }
        __syncwarp();  // osm reads done before next iteration's qsm writes
    }

    __shared__ float rs[256], rss[256];
    rs[tid] = lsum; rss[tid] = lsumsq;
    __syncthreads();
    for (int st = 128; st > 0; st >>= 1) {
        if (tid < st) { rs[tid] += rs[tid + st]; rss[tid] += rss[tid + st]; }
        __syncthreads();
    }
    if (tid == 0) {
        atomicAdd(&g_sum2[b],   (double)rs[0]);
        atomicAdd(&g_sumsq2[b], (double)rss[0]);
    }
}

// Final GroupNorm over y (in place on d_out)
__global__ void gn2_kernel(float* __restrict__ y,
                           const float* __restrict__ w,
                           const float* __restrict__ bb) {
    const double Nd = (double)NELEM_B;
    double mu0 = g_sum2[0] / Nd, v0d = g_sumsq2[0] / Nd - mu0 * mu0;
    double mu1 = g_sum2[1] / Nd, v1d = g_sumsq2[1] / Nd - mu1 * mu1;
    float is0 = (float)(1.0 / sqrt(v0d + 1e-5));
    float is1 = (float)(1.0 / sqrt(v1d + 1e-5));
    float m0 = (float)mu0, m1 = (float)mu1;

    const int half4  = NELEM_B / 4;
    const int total4 = 2 * half4;
    float4* p = (float4*)y;
    for (int i = blockIdx.x * blockDim.x + threadIdx.x; i < total4; i += gridDim.x * blockDim.x) {
        int b = (i >= half4);
        int e = (i - b * half4) * 4;
        int c = e / SPATIAL;
        float is = b ? is1 : is0;
        float mu = b ? m1  : m0;
        float sc = w[c] * is;
        float sh = bb[c] - mu * sc;
        float4 val = p[i];
        val.x = fmaf(val.x, sc, sh);
        val.y = fmaf(val.y, sc, sh);
        val.z = fmaf(val.z, sc, sh);
        val.w = fmaf(val.w, sc, sh);
        p[i] = val;
    }
}

extern "C" void kernel_launch(void* const* d_in, const int* in_sizes, int n_in,
                              void* d_out, int out_size) {
    const float* cost   = (const float*)d_in[0];
    const float* feat   = (const float*)d_in[1];
    const float* Wq     = (const float*)d_in[2];
    const float* Wk     = (const float*)d_in[3];
    const float* Wv     = (const float*)d_in[4];
    const float* Wo     = (const float*)d_in[5];
    const float* gn_in_w  = (const float*)d_in[6];
    const float* gn_in_b  = (const float*)d_in[7];
    const float* gn_out_w = (const float*)d_in[8];
    const float* gn_out_b = (const float*)d_in[9];
    const float* gamma    = (const float*)d_in[10];
    float* out = (float*)d_out;

    cudaFuncSetAttribute(main_kernel, cudaFuncAttributeMaxDynamicSharedMemorySize, SMEM_TOTAL);

    zero_acc_kernel<<<1, 32>>>();
    stats1_kernel<<<1024, 256>>>(cost);
    kv_kernel<<<64, 256>>>(feat, Wk, Wv);
    main_kernel<<<296, 256, SMEM_TOTAL>>>(cost, Wq, Wo, gn_in_w, gn_in_b, gamma, out);
    gn2_kernel<<<2368, 256>>>(out, gn_out_w, gn_out_b);
}

// round 8
// speedup vs baseline: 5.6709x; 1.3240x over previous
#include <cuda_runtime.h>
#include <cuda_bf16.h>
#include <cstdint>
#include <math.h>

#define SPATIAL 196608           // 24*64*128
#define NELEM_B (32 * SPATIAL)   // per-batch elements of cost

static __device__ double g_sum1[2], g_sumsq1[2], g_sum2[2], g_sumsq2[2];
static __device__ float g_K[2][2][256][16];   // [b][h][n][c], pre-scaled by 0.25*log2(e)
static __device__ float g_V[2][2][256][16];   // [b][h][n][j]

__global__ void zero_acc_kernel() {
    int i = threadIdx.x;
    if (i < 2) { g_sum1[i] = 0.0; g_sumsq1[i] = 0.0; g_sum2[i] = 0.0; g_sumsq2[i] = 0.0; }
}

// GroupNorm-1 statistics over cost, per batch. grid = 2*512 blocks, 256 thr.
__global__ void stats1_kernel(const float* __restrict__ cost) {
    int b   = blockIdx.x >> 9;
    int blk = blockIdx.x & 511;
    const float4* p = (const float4*)(cost + (size_t)b * NELEM_B);
    const int n4 = NELEM_B / 4;
    float s = 0.f, ss = 0.f;
    for (int i = blk * 256 + threadIdx.x; i < n4; i += 512 * 256) {
        float4 v = p[i];
        s  += (v.x + v.y) + (v.z + v.w);
        ss += (v.x * v.x + v.y * v.y) + (v.z * v.z + v.w * v.w);
    }
    __shared__ float rs[256], rss[256];
    rs[threadIdx.x] = s; rss[threadIdx.x] = ss;
    __syncthreads();
    for (int st = 128; st > 0; st >>= 1) {
        if (threadIdx.x < st) { rs[threadIdx.x] += rs[threadIdx.x + st]; rss[threadIdx.x] += rss[threadIdx.x + st]; }
        __syncthreads();
    }
    if (threadIdx.x == 0) {
        atomicAdd(&g_sum1[b],   (double)rs[0]);
        atomicAdd(&g_sumsq1[b], (double)rss[0]);
    }
}

// K/V projections. grid = 64 * 256 threads = 16384 = 2*2*256*16 outputs
__global__ void kv_kernel(const float* __restrict__ feat,
                          const float* __restrict__ Wk,
                          const float* __restrict__ Wv) {
    int idx = blockIdx.x * 256 + threadIdx.x;
    int c = idx & 15;
    int n = (idx >> 4) & 255;
    int h = (idx >> 12) & 1;
    int b = idx >> 13;
    const float* f  = feat + (size_t)b * 256 * 256 + n;  // stride 256 per fc
    const float* wk = Wk + (h * 16 + c) * 256;
    const float* wv = Wv + (h * 16 + c) * 256;
    float sk = 0.f, sv = 0.f;
    #pragma unroll 8
    for (int fc = 0; fc < 256; ++fc) {
        float fv = f[(size_t)fc * 256];
        sk = fmaf(wk[fc], fv, sk);
        sv = fmaf(wv[fc], fv, sv);
    }
    g_K[b][h][n][c] = sk * 0.36067376022224085f;  // DQK^-0.5 * log2(e) folded in
    g_V[b][h][n][c] = sv;
}

__device__ __forceinline__ void mma_bf16(float* c, const uint32_t* a, const uint32_t* b) {
    asm volatile(
        "mma.sync.aligned.m16n8k16.row.col.f32.bf16.bf16.f32 "
        "{%0,%1,%2,%3}, {%4,%5,%6,%7}, {%8,%9}, {%0,%1,%2,%3};\n"
        : "+f"(c[0]), "+f"(c[1]), "+f"(c[2]), "+f"(c[3])
        : "r"(a[0]), "r"(a[1]), "r"(a[2]), "r"(a[3]), "r"(b[0]), "r"(b[1]));
}

__device__ __forceinline__ void ldmatrix_x4(uint32_t& r0, uint32_t& r1, uint32_t& r2, uint32_t& r3, uint32_t addr) {
    asm volatile("ldmatrix.sync.aligned.m8n8.x4.shared.b16 {%0,%1,%2,%3}, [%4];"
        : "=r"(r0), "=r"(r1), "=r"(r2), "=r"(r3) : "r"(addr));
}

__device__ __forceinline__ uint32_t pack_bf16x2(float lo, float hi) {
    __nv_bfloat162 p = __float22bfloat162_rn(make_float2(lo, hi));
    return *(uint32_t*)&p;
}

__device__ __forceinline__ float ex2f(float x) {
    float y; asm("ex2.approx.f32 %0, %1;" : "=f"(y) : "f"(x)); return y;
}

// smem layout (bytes):
//   Ks  [2][256][24] bf16 : 0      .. 24576   (cols 0..15 valid)
//   Vt  [2][24][264] bf16 : 24576  .. 49920   (row16 = ones, 17..23 = zeros)
//   sGw/sGb 32 f32 each   : 49920  .. 50176
//   X scratch 8 w * 2560B : 50176  .. 70656   (bf16 [32 rows][40] pitch, cols 0..31 used)
#define SMEM_TOTAL 70656

__global__ void __launch_bounds__(256, 2) main_kernel(
    const float* __restrict__ cost,
    const float* __restrict__ Wq,
    const float* __restrict__ Wo,
    const float* __restrict__ gnw,
    const float* __restrict__ gnb,
    const float* __restrict__ gammap,
    float* __restrict__ out)
{
    extern __shared__ char sm[];
    __nv_bfloat16* Ks = (__nv_bfloat16*)sm;
    __nv_bfloat16* Vt = (__nv_bfloat16*)(sm + 24576);
    float* sGw = (float*)(sm + 49920);
    float* sGb = (float*)(sm + 50048);
    char*  scratch = sm + 50176;

    const int b   = blockIdx.x & 1;
    const int bi  = blockIdx.x >> 1;
    const int tid = threadIdx.x;
    const int wid = tid >> 5;
    const int lane = tid & 31;
    const int g  = lane >> 2;   // group id (row within fragment)
    const int tg = lane & 3;    // thread in group

    // ---- load K (token-major) and V (transposed, with ones column) to smem ----
    for (int i = tid; i < 512; i += 256) {          // i = h*256 + n
        int h = i >> 8, n = i & 255;
        const float* kp = &g_K[b][h][n][0];
        const float* vp = &g_V[b][h][n][0];
        __nv_bfloat16* krow = Ks + i * 24;
        #pragma unroll
        for (int c = 0; c < 16; ++c) krow[c] = __float2bfloat16(kp[c]);
        #pragma unroll
        for (int c = 0; c < 16; ++c) Vt[(h * 24 + c) * 264 + n] = __float2bfloat16(vp[c]);
        Vt[(h * 24 + 16) * 264 + n] = __float2bfloat16(1.0f);
        #pragma unroll
        for (int c = 17; c < 24; ++c) Vt[(h * 24 + c) * 264 + n] = __float2bfloat16(0.0f);
    }
    if (tid < 32) {
        double mu  = g_sum1[b] / (double)NELEM_B;
        double var = g_sumsq1[b] / (double)NELEM_B - mu * mu;
        float is = (float)(1.0 / sqrt(var + 1e-5));
        float sc = gnw[tid] * is;
        sGw[tid] = sc;
        sGb[tid] = gnb[tid] - (float)mu * sc;
    }
    __syncthreads();

    // ---- persistent B-fragments of Wq and Wo (col-major k16n8 tiles) ----
    // q[v,o] = sum_c X[v,c] Wq[o,c]: B[n=o][k=c]; y[v,c] = sum_m ao[v,m] Wo[c,m]: B[n=c][k=m]
    uint32_t bwq[4][2][2], bwo[4][2][2];
    #pragma unroll
    for (int nt = 0; nt < 4; ++nt)
        #pragma unroll
        for (int kc = 0; kc < 2; ++kc) {
            const float* wq = Wq + (nt * 8 + g) * 32 + kc * 16 + tg * 2;
            const float* wo = Wo + (nt * 8 + g) * 32 + kc * 16 + tg * 2;
            bwq[nt][kc][0] = pack_bf16x2(wq[0], wq[1]);
            bwq[nt][kc][1] = pack_bf16x2(wq[8], wq[9]);
            bwo[nt][kc][0] = pack_bf16x2(wo[0], wo[1]);
            bwo[nt][kc][1] = pack_bf16x2(wo[8], wo[9]);
        }

    const float gamma = *gammap;
    const float* costb = cost + (size_t)b * NELEM_B;
    float* outb = out + (size_t)b * NELEM_B;

    __nv_bfloat16* X = (__nv_bfloat16*)(scratch + wid * 2560);  // [32][40] bf16
    const uint32_t xu = (uint32_t)__cvta_generic_to_shared(X);

    float lsum = 0.f, lsumsq = 0.f;

    for (int super = bi; super < 768; super += 148) {
        const int vbase = super * 256 + wid * 32;
        const int v = vbase + lane;

        // ---- GN1-normalize -> bf16 X in smem ----
        {
            uint32_t xp[16];
            #pragma unroll
            for (int j = 0; j < 16; ++j) {
                float a0 = fmaf(costb[(size_t)(2 * j) * SPATIAL + v],     sGw[2 * j],     sGb[2 * j]);
                float a1 = fmaf(costb[(size_t)(2 * j + 1) * SPATIAL + v], sGw[2 * j + 1], sGb[2 * j + 1]);
                xp[j] = pack_bf16x2(a0, a1);
            }
            uint4* xr = (uint4*)((char*)X + lane * 80);
            xr[0] = make_uint4(xp[0], xp[1], xp[2], xp[3]);
            xr[1] = make_uint4(xp[4], xp[5], xp[6], xp[7]);
            xr[2] = make_uint4(xp[8], xp[9], xp[10], xp[11]);
            xr[3] = make_uint4(xp[12], xp[13], xp[14], xp[15]);
        }
        __syncwarp();

        // ---- A-fragments of X via ldmatrix ----
        uint32_t aX[2][2][4];
        {
            const uint32_t lrow = (uint32_t)(lane & 15) * 80 + (uint32_t)(lane >> 4) * 16;
            #pragma unroll
            for (int mt = 0; mt < 2; ++mt)
                #pragma unroll
                for (int kc = 0; kc < 2; ++kc)
                    ldmatrix_x4(aX[mt][kc][0], aX[mt][kc][1], aX[mt][kc][2], aX[mt][kc][3],
                                xu + (uint32_t)mt * 1280 + (uint32_t)kc * 32 + lrow);
        }
        __syncwarp();  // X reads done before next iteration's writes

        // ---- q = X @ Wq^T on tensor cores; C-frag cols (h*16+dqk) ----
        float qc[2][4][4];
        #pragma unroll
        for (int mt = 0; mt < 2; ++mt)
            #pragma unroll
            for (int nt = 0; nt < 4; ++nt) {
                #pragma unroll
                for (int i = 0; i < 4; ++i) qc[mt][nt][i] = 0.f;
                mma_bf16(qc[mt][nt], aX[mt][0], bwq[nt][0]);
                mma_bf16(qc[mt][nt], aX[mt][1], bwq[nt][1]);
            }

        // C-frag -> A-frag identity: per-head QK A operands
        uint32_t aq[2][2][4];
        #pragma unroll
        for (int h = 0; h < 2; ++h)
            #pragma unroll
            for (int mt = 0; mt < 2; ++mt) {
                aq[h][mt][0] = pack_bf16x2(qc[mt][2 * h][0],     qc[mt][2 * h][1]);
                aq[h][mt][1] = pack_bf16x2(qc[mt][2 * h][2],     qc[mt][2 * h][3]);
                aq[h][mt][2] = pack_bf16x2(qc[mt][2 * h + 1][0], qc[mt][2 * h + 1][1]);
                aq[h][mt][3] = pack_bf16x2(qc[mt][2 * h + 1][2], qc[mt][2 * h + 1][3]);
            }

        // ---- attention per head; normalized output packed to A-frags for Wo ----
        uint32_t aA[2][2][4];   // [mt][kc=h][4]
        #pragma unroll
        for (int h = 0; h < 2; ++h) {
            const __nv_bfloat16* Kh = Ks + h * 256 * 24;
            const __nv_bfloat16* Vh = Vt + h * 24 * 264;
            float co[2][3][4];
            #pragma unroll
            for (int mt = 0; mt < 2; ++mt)
                #pragma unroll
                for (int nv = 0; nv < 3; ++nv)
                    #pragma unroll
                    for (int i = 0; i < 4; ++i) co[mt][nv][i] = 0.f;

            for (int chk = 0; chk < 16; ++chk) {
                const int n0 = chk * 16;
                uint32_t bk[2][2];
                #pragma unroll
                for (int nt = 0; nt < 2; ++nt) {
                    const __nv_bfloat16* kp = Kh + (n0 + nt * 8 + g) * 24 + tg * 2;
                    bk[nt][0] = *(const uint32_t*)kp;
                    bk[nt][1] = *(const uint32_t*)(kp + 8);
                }
                float cl[2][2][4];
                #pragma unroll
                for (int mt = 0; mt < 2; ++mt)
                    #pragma unroll
                    for (int nt = 0; nt < 2; ++nt) {
                        #pragma unroll
                        for (int i = 0; i < 4; ++i) cl[mt][nt][i] = 0.f;
                        mma_bf16(cl[mt][nt], aq[h][mt], bk[nt]);
                    }
                // exp2 (log2e folded into K); logits O(0.3): no max shift needed
                #pragma unroll
                for (int mt = 0; mt < 2; ++mt)
                    #pragma unroll
                    for (int nt = 0; nt < 2; ++nt)
                        #pragma unroll
                        for (int i = 0; i < 4; ++i)
                            cl[mt][nt][i] = ex2f(cl[mt][nt][i]);
                uint32_t ap[2][4];
                #pragma unroll
                for (int mt = 0; mt < 2; ++mt) {
                    ap[mt][0] = pack_bf16x2(cl[mt][0][0], cl[mt][0][1]);
                    ap[mt][1] = pack_bf16x2(cl[mt][0][2], cl[mt][0][3]);
                    ap[mt][2] = pack_bf16x2(cl[mt][1][0], cl[mt][1][1]);
                    ap[mt][3] = pack_bf16x2(cl[mt][1][2], cl[mt][1][3]);
                }
                uint32_t bv[3][2];
                #pragma unroll
                for (int nv = 0; nv < 3; ++nv) {
                    const __nv_bfloat16* vp = Vh + (nv * 8 + g) * 264 + n0 + tg * 2;
                    bv[nv][0] = *(const uint32_t*)vp;
                    bv[nv][1] = *(const uint32_t*)(vp + 8);
                }
                #pragma unroll
                for (int mt = 0; mt < 2; ++mt)
                    #pragma unroll
                    for (int nv = 0; nv < 3; ++nv)
                        mma_bf16(co[mt][nv], ap[mt], bv[nv]);
            }

            // normalize (ones-column denominator: dv16 -> tile 2, col 0) and pack
            #pragma unroll
            for (int mt = 0; mt < 2; ++mt) {
                float dlo = __shfl_sync(0xffffffffu, co[mt][2][0], lane & ~3);
                float dhi = __shfl_sync(0xffffffffu, co[mt][2][2], lane & ~3);
                float ilo = 1.f / dlo, ihi = 1.f / dhi;
                aA[mt][h][0] = pack_bf16x2(co[mt][0][0] * ilo, co[mt][0][1] * ilo);
                aA[mt][h][1] = pack_bf16x2(co[mt][0][2] * ihi, co[mt][0][3] * ihi);
                aA[mt][h][2] = pack_bf16x2(co[mt][1][0] * ilo, co[mt][1][1] * ilo);
                aA[mt][h][3] = pack_bf16x2(co[mt][1][2] * ihi, co[mt][1][3] * ihi);
            }
        }

        // ---- y = ao @ Wo^T on tensor cores ----
        float yc[2][4][4];
        #pragma unroll
        for (int mt = 0; mt < 2; ++mt)
            #pragma unroll
            for (int nt = 0; nt < 4; ++nt) {
                #pragma unroll
                for (int i = 0; i < 4; ++i) yc[mt][nt][i] = 0.f;
                mma_bf16(yc[mt][nt], aA[mt][0], bwo[nt][0]);
                mma_bf16(yc[mt][nt], aA[mt][1], bwo[nt][1]);
            }

        // ---- epilogue directly on fragments: residual + store + GN2 stats ----
        // frag element (i): rows vbase+mt*16+g (+8 for i>=2), cols nt*8+tg*2 (+1 for odd i)
        #pragma unroll
        for (int mt = 0; mt < 2; ++mt) {
            const int r0 = vbase + mt * 16 + g;
            #pragma unroll
            for (int nt = 0; nt < 4; ++nt) {
                const int c0 = nt * 8 + tg * 2;
                const size_t i00 = (size_t)c0 * SPATIAL + r0;
                const size_t i10 = i00 + SPATIAL;            // col c0+1
                float y0 = fmaf(gamma, yc[mt][nt][0], costb[i00]);
                float y1 = fmaf(gamma, yc[mt][nt][1], costb[i10]);
                float y2 = fmaf(gamma, yc[mt][nt][2], costb[i00 + 8]);
                float y3 = fmaf(gamma, yc[mt][nt][3], costb[i10 + 8]);
                outb[i00]     = y0;
                outb[i10]     = y1;
                outb[i00 + 8] = y2;
                outb[i10 + 8] = y3;
                lsum += (y0 + y1) + (y2 + y3);
                lsumsq = fmaf(y0, y0, lsumsq);
                lsumsq = fmaf(y1, y1, lsumsq);
                lsumsq = fmaf(y2, y2, lsumsq);
                lsumsq = fmaf(y3, y3, lsumsq);
            }
        }
    }

    __shared__ float rs[256], rss[256];
    rs[tid] = lsum; rss[tid] = lsumsq;
    __syncthreads();
    for (int st = 128; st > 0; st >>= 1) {
        if (tid < st) { rs[tid] += rs[tid + st]; rss[tid] += rss[tid + st]; }
        __syncthreads();
    }
    if (tid == 0) {
        atomicAdd(&g_sum2[b],   (double)rs[0]);
        atomicAdd(&g_sumsq2[b], (double)rss[0]);
    }
}

// Final GroupNorm over y (in place on d_out)
__global__ void gn2_kernel(float* __restrict__ y,
                           const float* __restrict__ w,
                           const float* __restrict__ bb) {
    const double Nd = (double)NELEM_B;
    double mu0 = g_sum2[0] / Nd, v0d = g_sumsq2[0] / Nd - mu0 * mu0;
    double mu1 = g_sum2[1] / Nd, v1d = g_sumsq2[1] / Nd - mu1 * mu1;
    float is0 = (float)(1.0 / sqrt(v0d + 1e-5));
    float is1 = (float)(1.0 / sqrt(v1d + 1e-5));
    float m0 = (float)mu0, m1 = (float)mu1;

    const int half4  = NELEM_B / 4;
    const int total4 = 2 * half4;
    float4* p = (float4*)y;
    for (int i = blockIdx.x * blockDim.x + threadIdx.x; i < total4; i += gridDim.x * blockDim.x) {
        int b = (i >= half4);
        int e = (i - b * half4) * 4;
        int c = e / SPATIAL;
        float is = b ? is1 : is0;
        float mu = b ? m1  : m0;
        float sc = w[c] * is;
        float sh = bb[c] - mu * sc;
        float4 val = p[i];
        val.x = fmaf(val.x, sc, sh);
        val.y = fmaf(val.y, sc, sh);
        val.z = fmaf(val.z, sc, sh);
        val.w = fmaf(val.w, sc, sh);
        p[i] = val;
    }
}

extern "C" void kernel_launch(void* const* d_in, const int* in_sizes, int n_in,
                              void* d_out, int out_size) {
    const float* cost   = (const float*)d_in[0];
    const float* feat   = (const float*)d_in[1];
    const float* Wq     = (const float*)d_in[2];
    const float* Wk     = (const float*)d_in[3];
    const float* Wv     = (const float*)d_in[4];
    const float* Wo     = (const float*)d_in[5];
    const float* gn_in_w  = (const float*)d_in[6];
    const float* gn_in_b  = (const float*)d_in[7];
    const float* gn_out_w = (const float*)d_in[8];
    const float* gn_out_b = (const float*)d_in[9];
    const float* gamma    = (const float*)d_in[10];
    float* out = (float*)d_out;

    cudaFuncSetAttribute(main_kernel, cudaFuncAttributeMaxDynamicSharedMemorySize, SMEM_TOTAL);

    zero_acc_kernel<<<1, 32>>>();
    stats1_kernel<<<1024, 256>>>(cost);
    kv_kernel<<<64, 256>>>(feat, Wk, Wv);
    main_kernel<<<296, 256, SMEM_TOTAL>>>(cost, Wq, Wo, gn_in_w, gn_in_b, gamma, out);
    gn2_kernel<<<2368, 256>>>(out, gn_out_w, gn_out_b);
}